// round 12
// baseline (speedup 1.0000x reference)
#include <cuda_runtime.h>

// CrossCompress: B=16384 rows, D=128.
// item_out   = v*(e.w_vv) + e*(v.w_ev) + bias_v
// entity_out = v*(e.w_ve) + e*(v.w_ee) + bias_e
//
// R12: R3 geometry (lane-per-float4, 4 rows/warp, 8 front-batched LDG.128,
// 128-thr blocks, grid 1024) with the reduce/combine/store pipeline
// restructured per-row: row r's stores issue right after its own 5-level
// butterfly instead of after all 80 shuffles, overlapping STG drain with
// the remaining reduction work and shortening v/e register live ranges.

#define B_ROWS 16384
#define D_DIM  128
#define RPW    4

__global__ __launch_bounds__(128)
void crosscompress_kernel(const float4* __restrict__ v_in,
                          const float4* __restrict__ e_in,
                          const float4* __restrict__ w_vv,
                          const float4* __restrict__ w_ve,
                          const float4* __restrict__ w_ev,
                          const float4* __restrict__ w_ee,
                          const float4* __restrict__ bias_v,
                          const float4* __restrict__ bias_e,
                          float4* __restrict__ out_item,
                          float4* __restrict__ out_ent)
{
    const int gtid = blockIdx.x * blockDim.x + threadIdx.x;
    const int warp = gtid >> 5;
    const int lane = gtid & 31;
    const int idx0 = (warp * RPW) * 32 + lane;

    // Front-batched row loads: 8 independent LDG.128 (MLP_p1=8)
    float4 v4[RPW], e4[RPW];
    #pragma unroll
    for (int r = 0; r < RPW; r++) {
        v4[r] = v_in[idx0 + r * 32];
        e4[r] = e_in[idx0 + r * 32];
    }

    // Weights + biases (L1-resident), issued behind row loads
    const float4 wvv = __ldg(&w_vv[lane]);
    const float4 wev = __ldg(&w_ev[lane]);
    const float4 wve = __ldg(&w_ve[lane]);
    const float4 wee = __ldg(&w_ee[lane]);
    const float4 bv  = __ldg(&bias_v[lane]);
    const float4 be  = __ldg(&bias_e[lane]);

    // Per-row: partials -> butterfly -> combine -> store.
    // Row r's stores issue as soon as its own reduction finishes; the
    // compiler can overlap row r+1's shuffles with row r's store drain.
    #pragma unroll
    for (int r = 0; r < RPW; r++) {
        float d_vv = e4[r].x*wvv.x + e4[r].y*wvv.y + e4[r].z*wvv.z + e4[r].w*wvv.w;
        float d_ev = v4[r].x*wev.x + v4[r].y*wev.y + v4[r].z*wev.z + v4[r].w*wev.w;
        float d_ve = e4[r].x*wve.x + e4[r].y*wve.y + e4[r].z*wve.z + e4[r].w*wve.w;
        float d_ee = v4[r].x*wee.x + v4[r].y*wee.y + v4[r].z*wee.z + v4[r].w*wee.w;

        #pragma unroll
        for (int off = 16; off > 0; off >>= 1) {
            d_vv += __shfl_xor_sync(0xFFFFFFFFu, d_vv, off);
            d_ev += __shfl_xor_sync(0xFFFFFFFFu, d_ev, off);
            d_ve += __shfl_xor_sync(0xFFFFFFFFu, d_ve, off);
            d_ee += __shfl_xor_sync(0xFFFFFFFFu, d_ee, off);
        }

        const int idx = idx0 + r * 32;
        float4 oi, oe;
        oi.x = v4[r].x*d_vv + e4[r].x*d_ev + bv.x;
        oi.y = v4[r].y*d_vv + e4[r].y*d_ev + bv.y;
        oi.z = v4[r].z*d_vv + e4[r].z*d_ev + bv.z;
        oi.w = v4[r].w*d_vv + e4[r].w*d_ev + bv.w;
        oe.x = v4[r].x*d_ve + e4[r].x*d_ee + be.x;
        oe.y = v4[r].y*d_ve + e4[r].y*d_ee + be.y;
        oe.z = v4[r].z*d_ve + e4[r].z*d_ee + be.z;
        oe.w = v4[r].w*d_ve + e4[r].w*d_ee + be.w;

        out_item[idx] = oi;
        out_ent[idx]  = oe;
    }
}

extern "C" void kernel_launch(void* const* d_in, const int* in_sizes, int n_in,
                              void* d_out, int out_size)
{
    const float4* v_in   = (const float4*)d_in[0];
    const float4* e_in   = (const float4*)d_in[1];
    const float4* w_vv   = (const float4*)d_in[2];
    const float4* w_ve   = (const float4*)d_in[3];
    const float4* w_ev   = (const float4*)d_in[4];
    const float4* w_ee   = (const float4*)d_in[5];
    const float4* bias_v = (const float4*)d_in[6];
    const float4* bias_e = (const float4*)d_in[7];

    float* out = (float*)d_out;
    float4* out_item = (float4*)out;
    float4* out_ent  = (float4*)(out + B_ROWS * D_DIM);

    // 4 warps/block, 4 rows/warp -> 16 rows/block -> 1024 blocks
    const int threads = 128;
    const int blocks  = B_ROWS / (4 * RPW);   // 1024

    crosscompress_kernel<<<blocks, threads>>>(v_in, e_in, w_vv, w_ve, w_ev, w_ee,
                                              bias_v, bias_e, out_item, out_ent);
}

// round 13
// speedup vs baseline: 1.0370x; 1.0370x over previous
#include <cuda_runtime.h>

// CrossCompress: B=16384 rows, D=128.
// item_out   = v*(e.w_vv) + e*(v.w_ev) + bias_v
// entity_out = v*(e.w_ve) + e*(v.w_ee) + bias_e
//
// R13: anti-spread variant. R3's iteration shape (4 rows/warp, MLP=8 batched
// LDG.128, 5-level butterfly, fused combine+store) executed TWICE per warp
// (8 rows total). After iteration 1 warps desynchronize, so iteration-2 load
// batches enter the per-SM L1tex queue staggered instead of as one grid-wide
// burst — targeting the cross-CTA queue-contention spread (spr~2x) that the
// T_chip model says dominates this kernel's runtime.

#define B_ROWS 16384
#define D_DIM  128
#define RPW    4     // rows per iteration
#define NITER  2     // iterations per warp

__global__ __launch_bounds__(128)
void crosscompress_kernel(const float4* __restrict__ v_in,
                          const float4* __restrict__ e_in,
                          const float4* __restrict__ w_vv,
                          const float4* __restrict__ w_ve,
                          const float4* __restrict__ w_ev,
                          const float4* __restrict__ w_ee,
                          const float4* __restrict__ bias_v,
                          const float4* __restrict__ bias_e,
                          float4* __restrict__ out_item,
                          float4* __restrict__ out_ent)
{
    const int gtid = blockIdx.x * blockDim.x + threadIdx.x;
    const int warp = gtid >> 5;
    const int lane = gtid & 31;

    // Weights + biases once per warp (L1-resident)
    const float4 wvv = __ldg(&w_vv[lane]);
    const float4 wev = __ldg(&w_ev[lane]);
    const float4 wve = __ldg(&w_ve[lane]);
    const float4 wee = __ldg(&w_ee[lane]);
    const float4 bv  = __ldg(&bias_v[lane]);
    const float4 be  = __ldg(&bias_e[lane]);

    #pragma unroll
    for (int it = 0; it < NITER; it++) {
        const int idx0 = ((warp * NITER + it) * RPW) * 32 + lane;

        // Batched row loads for this iteration: 8 independent LDG.128
        float4 v4[RPW], e4[RPW];
        #pragma unroll
        for (int r = 0; r < RPW; r++) {
            v4[r] = v_in[idx0 + r * 32];
            e4[r] = e_in[idx0 + r * 32];
        }

        // 16 independent per-lane partial dots
        float d_vv[RPW], d_ev[RPW], d_ve[RPW], d_ee[RPW];
        #pragma unroll
        for (int r = 0; r < RPW; r++) {
            d_vv[r] = e4[r].x*wvv.x + e4[r].y*wvv.y + e4[r].z*wvv.z + e4[r].w*wvv.w;
            d_ev[r] = v4[r].x*wev.x + v4[r].y*wev.y + v4[r].z*wev.z + v4[r].w*wev.w;
            d_ve[r] = e4[r].x*wve.x + e4[r].y*wve.y + e4[r].z*wve.z + e4[r].w*wve.w;
            d_ee[r] = v4[r].x*wee.x + v4[r].y*wee.y + v4[r].z*wee.z + v4[r].w*wee.w;
        }

        // Butterfly-reduce all 16 values (16 parallel chains per level)
        #pragma unroll
        for (int off = 16; off > 0; off >>= 1) {
            #pragma unroll
            for (int r = 0; r < RPW; r++) {
                d_vv[r] += __shfl_xor_sync(0xFFFFFFFFu, d_vv[r], off);
                d_ev[r] += __shfl_xor_sync(0xFFFFFFFFu, d_ev[r], off);
                d_ve[r] += __shfl_xor_sync(0xFFFFFFFFu, d_ve[r], off);
                d_ee[r] += __shfl_xor_sync(0xFFFFFFFFu, d_ee[r], off);
            }
        }

        // Combine + store
        #pragma unroll
        for (int r = 0; r < RPW; r++) {
            const int idx = idx0 + r * 32;
            float4 oi, oe;
            oi.x = v4[r].x*d_vv[r] + e4[r].x*d_ev[r] + bv.x;
            oi.y = v4[r].y*d_vv[r] + e4[r].y*d_ev[r] + bv.y;
            oi.z = v4[r].z*d_vv[r] + e4[r].z*d_ev[r] + bv.z;
            oi.w = v4[r].w*d_vv[r] + e4[r].w*d_ev[r] + bv.w;
            oe.x = v4[r].x*d_ve[r] + e4[r].x*d_ee[r] + be.x;
            oe.y = v4[r].y*d_ve[r] + e4[r].y*d_ee[r] + be.y;
            oe.z = v4[r].z*d_ve[r] + e4[r].z*d_ee[r] + be.z;
            oe.w = v4[r].w*d_ve[r] + e4[r].w*d_ee[r] + be.w;
            out_item[idx] = oi;
            out_ent[idx]  = oe;
        }
    }
}

extern "C" void kernel_launch(void* const* d_in, const int* in_sizes, int n_in,
                              void* d_out, int out_size)
{
    const float4* v_in   = (const float4*)d_in[0];
    const float4* e_in   = (const float4*)d_in[1];
    const float4* w_vv   = (const float4*)d_in[2];
    const float4* w_ve   = (const float4*)d_in[3];
    const float4* w_ev   = (const float4*)d_in[4];
    const float4* w_ee   = (const float4*)d_in[5];
    const float4* bias_v = (const float4*)d_in[6];
    const float4* bias_e = (const float4*)d_in[7];

    float* out = (float*)d_out;
    float4* out_item = (float4*)out;
    float4* out_ent  = (float4*)(out + B_ROWS * D_DIM);

    // 4 warps/block, 8 rows/warp (2 iter x 4) -> 32 rows/block -> 512 blocks
    const int threads = 128;
    const int blocks  = B_ROWS / (4 * RPW * NITER);   // 512

    crosscompress_kernel<<<blocks, threads>>>(v_in, e_in, w_vv, w_ve, w_ev, w_ee,
                                              bias_v, bias_e, out_item, out_ent);
}